// round 7
// baseline (speedup 1.0000x reference)
#include <cuda_runtime.h>

// ---------------------------------------------------------------------------
// ContrastiveCRFLoss — B200 (sm_100a), round 7.
//
// Exact-zero sparsity: out[n,a,b] != ±0.0 only for integer pixel-dist^2
// cd <= 105 (~6k of 1M pairs, batch independent, includes diagonal).
//
// k1 gp_k   : bid<4  per-row pair enumeration (SMEM coords, no atomics)
//             else   R2-measured gather mapping: warp = 32 consecutive
//                    samples in ONE plane (load locality), coalesced stores
//                    to d_tmp[w][s]  (w: 0..863 = n*27+k, 864..959 = n*3+ch)
// k2 tz_k   : bid<960   SMEM-tiled transpose d_tmp[w][s] -> d_recT[s][w'][n]
//             else      zero-fill 128MB output (plain float4 stores)
// k3 sparse : 32-thread block per row a, lane = batch n; coalesced reads.
// ---------------------------------------------------------------------------

#define NB     32
#define KC     27
#define NS     1000
#define NSP    1024
#define HW     256
#define CD_MAX 105.0f
#define ROWCAP 64

#define PAIRB  4
#define GATB   3375                  // 864000 / 256
#define TRB    960                   // 30 words x 32 s-tiles
#define ZFB    4096

__device__ float    d_tmp [960 * NSP];        // [w][s] gather staging, ~3.9MB
__device__ float    d_recT[NS * 32 * NB];     // [s][w][n], 4MB
__device__ unsigned d_rowPair[NS * ROWCAP];
__device__ int      d_rowCnt[NS];

// ---------------------------------------------------------------------------
// k1: pairs + gather
// ---------------------------------------------------------------------------
__global__ void __launch_bounds__(256)
gp_k(const float* __restrict__ guidance,
     const float* __restrict__ clusters,
     const int*   __restrict__ coords) {
    const int bid = blockIdx.x;
    const int tid = threadIdx.x;

    if (bid < PAIRB) {
        __shared__ float sr[NS], sc[NS];
        for (int i = tid; i < NS; i += 256) {
            sr[i] = (float)__ldg(&coords[i]);
            sc[i] = (float)__ldg(&coords[NS + i]);
        }
        __syncthreads();

        int a = bid * 256 + tid;
        if (a < NS) {
            float arf = sr[a], acf = sc[a];
            int cnt = 0;
            unsigned* row = d_rowPair + a * ROWCAP;
            #pragma unroll 4
            for (int b = 0; b < NS; b++) {
                float dr = arf - sr[b];
                float dc = acf - sc[b];
                float cd = dr * dr + dc * dc;
                if (cd <= CD_MAX && cnt < ROWCAP) {
                    row[cnt] = ((unsigned)(int)cd << 10) | (unsigned)b;
                    cnt++;
                }
            }
            d_rowCnt[a] = cnt;
        }
        return;
    }

    // ---- gather (R2-measured mapping): idx = nk*NS + s, s fastest ----
    int idx = (bid - PAIRB) * 256 + tid;        // [0, 864000)
    int nk  = idx / NS;                         // n*27 + k  (warp-uniform-ish)
    int s   = idx - nk * NS;

    int r  = __ldg(&coords[s]);
    int c  = __ldg(&coords[NS + s]);
    int px = r * HW + c;

    d_tmp[nk * NSP + s] = __ldg(&clusters[((size_t)nk << 16) + px]);

    if (idx < NB * NS) {                         // nk == n here
        int n = nk;
        const float* gb = guidance + (((size_t)n * 3) << 16) + px;
        float g0 = __ldg(gb);
        float g1 = __ldg(gb + (1 << 16));
        float g2 = __ldg(gb + (2 << 16));
        d_tmp[(864 + n * 3 + 0) * NSP + s] = g0;
        d_tmp[(864 + n * 3 + 1) * NSP + s] = g1;
        d_tmp[(864 + n * 3 + 2) * NSP + s] = g2;
    }
}

// ---------------------------------------------------------------------------
// k2: transpose + zfill
// ---------------------------------------------------------------------------
__global__ void __launch_bounds__(256)
tz_k(float4* __restrict__ out, int n4) {
    const int bid = blockIdx.x;
    const int tid = threadIdx.x;

    if (bid < TRB) {
        // ---- transpose: word wk (0..29), s-tile st (0..31), 32n x 32s ----
        __shared__ float T[32][33];
        const int wk = bid % 30;
        const int st = bid / 30;
        const int s0 = st * 32;
        const int w    = tid >> 5;              // warp 0..7
        const int lane = tid & 31;

        // load: 4 n-rows per warp, lanes sweep s (coalesced)
        #pragma unroll
        for (int q = 0; q < 4; q++) {
            int n = w * 4 + q;
            int srcRow = (wk < KC) ? (n * KC + wk) : (864 + n * 3 + (wk - KC));
            int s = s0 + lane;
            T[n][lane] = (s < NS) ? d_tmp[srcRow * NSP + s] : 0.f;
        }
        __syncthreads();

        // store: 4 s-rows per warp, lanes sweep n (coalesced 128B)
        #pragma unroll
        for (int q = 0; q < 4; q++) {
            int sl = w * 4 + q;
            int s  = s0 + sl;
            if (s < NS)
                d_recT[(size_t)s * 1024 + wk * 32 + lane] = T[lane][sl];
        }
    } else {
        // ---- zero-fill output ----
        int zidx = (bid - TRB) * 256 + tid;
        float4 z = make_float4(0.f, 0.f, 0.f, 0.f);
        #pragma unroll
        for (int it = 0; it < 8; it++) {
            int i = zidx + it * (ZFB * 256);
            if (i < n4) out[i] = z;
        }
    }
}

// ---------------------------------------------------------------------------
// k3: sparse compute — one 32-thread block per row a, lane = batch n
// ---------------------------------------------------------------------------
__global__ void __launch_bounds__(32)
sparse_k(float* __restrict__ out) {
    const int a    = blockIdx.x;
    const int lane = threadIdx.x;

    const int cnt = __ldg(&d_rowCnt[a]);

    const float* raBase = d_recT + (size_t)a * 1024 + lane;
    float ra[30];
    #pragma unroll
    for (int w = 0; w < 30; w++) ra[w] = __ldg(raBase + w * NB);

    const unsigned* row = d_rowPair + a * ROWCAP;

    for (int slot = 0; slot < cnt; slot++) {
        unsigned e = __ldg(&row[slot]);
        int   b  = (int)(e & 1023u);
        float cd = (float)(e >> 10);

        const float* rbBase = d_recT + (size_t)b * 1024 + lane;

        float dot = 0.f;
        #pragma unroll
        for (int k = 0; k < KC; k++)
            dot = fmaf(ra[k], __ldg(rbBase + k * NB), dot);

        float gd = 0.f;
        #pragma unroll
        for (int ch = 0; ch < 3; ch++) {
            float d = ra[27 + ch] - __ldg(rbBase + (27 + ch) * NB);
            gd = fmaf(d, d, gd);
        }

        float s1 = 10.0f * __expf(-cd - gd * 3.33333333f);
        float s2 = 3.0f  * __expf(-10.0f * cd);

        out[((size_t)lane * NS + a) * NS + b] = -dot * (s1 + s2);
    }
}

// ---------------------------------------------------------------------------
extern "C" void kernel_launch(void* const* d_in, const int* in_sizes, int n_in,
                              void* d_out, int out_size) {
    const float* guidance = (const float*)d_in[0];
    const float* clusters = (const float*)d_in[1];
    const int*   coords   = (const int*)d_in[2];
    float* out = (float*)d_out;

    gp_k<<<PAIRB + GATB, 256>>>(guidance, clusters, coords);
    tz_k<<<TRB + ZFB, 256>>>((float4*)out, out_size / 4);
    sparse_k<<<NS, 32>>>(out);
}

// round 8
// speedup vs baseline: 1.5482x; 1.5482x over previous
#include <cuda_runtime.h>

// ---------------------------------------------------------------------------
// ContrastiveCRFLoss — B200 (sm_100a), round 8.
//
// = the round-4 kernel (59.4us, only config measured at the DRAM byte floor)
//   with the 9.5us bitonic sort replaced by a ~1.5us counting sort.
//   fused_k / sparse_k are verbatim from the 59.4us version.
//
// Exact-zero sparsity: out[n,a,b] != -0.0 only for integer pixel-dist^2
// cd <= 105 (~6k of 1M ordered pairs, batch independent).
// ---------------------------------------------------------------------------

#define NB    32
#define KC    27
#define NS    1000
#define HW    256
#define MAXP  32768
#define CD_MAX 105.0f

#define GB 3375                    // gather blocks: 864000 threads
#define ZB 4096                    // zfill blocks:  1M threads x 8 float4
#define PB 4096                    // pairs blocks:  1M threads
#define NBLK (GB + ZB + PB)

// record table, transposed: d_recT[s][word][n], word 0..26=C, 27..29=G
__device__ float    d_recT[NS * 32 * NB];     // 4 MB
__device__ int      d_order[1024];            // spatially sorted sample ids
__device__ unsigned d_pairs[MAXP];            // (a<<10)|b
__device__ float    d_pcd[MAXP];              // cd per pair
__device__ int      d_npairs;

// ---------------------------------------------------------------------------
// k0: counting sort of samples by spatial bin (px >> 6), one block.
// Replaces the 9.5us bitonic sort; output permutation only affects which
// thread gathers which sample, never the results.
// ---------------------------------------------------------------------------
__global__ void __launch_bounds__(1024)
prep_k(const int* __restrict__ coords) {
    __shared__ int hist[1024];
    __shared__ int base[1024];
    __shared__ int wsum[32];

    const int tid  = threadIdx.x;
    const int lane = tid & 31;
    const int w    = tid >> 5;

    if (tid == 0) d_npairs = 0;
    hist[tid] = 0;
    __syncthreads();

    int bin = 0, rank = 0;
    if (tid < NS) {
        int r = __ldg(&coords[tid]);
        int c = __ldg(&coords[NS + tid]);
        bin  = (r * 256 + c) >> 6;                 // 0..1023
        rank = atomicAdd(&hist[bin], 1);
    }
    __syncthreads();

    // exclusive scan of hist[1024]
    int cnt = hist[tid];
    int v = cnt;
    #pragma unroll
    for (int o = 1; o < 32; o <<= 1) {
        int t = __shfl_up_sync(0xffffffffu, v, o);
        if (lane >= o) v += t;                     // inclusive within warp
    }
    if (lane == 31) wsum[w] = v;
    __syncthreads();
    if (tid < 32) {
        int s = wsum[tid];
        #pragma unroll
        for (int o = 1; o < 32; o <<= 1) {
            int t = __shfl_up_sync(0xffffffffu, s, o);
            if (tid >= o) s += t;
        }
        wsum[tid] = s;                             // inclusive warp sums
    }
    __syncthreads();
    int warpOff = (w == 0) ? 0 : wsum[w - 1];
    base[tid] = warpOff + v - cnt;                 // exclusive scan
    __syncthreads();

    if (tid < NS)
        d_order[base[bin] + rank] = tid;
}

// ---------------------------------------------------------------------------
// k1: fused gather + zfill + pairs  (verbatim from the 59.4us kernel)
// ---------------------------------------------------------------------------
__global__ void __launch_bounds__(256)
fused_k(const float* __restrict__ guidance,
        const float* __restrict__ clusters,
        const int*   __restrict__ coords,
        float4* __restrict__ out, int n4) {
    int bid = blockIdx.x;
    int tid = threadIdx.x;

    if (bid < GB) {
        // ---- gather: idx = (n*KC + k)*NS + sIdx, sIdx fastest (sorted) ----
        int idx = bid * 256 + tid;                 // < 864000 exactly
        int nk   = idx / NS;                       // n*27 + k
        int sIdx = idx - nk * NS;
        int n = nk / KC;
        int k = nk - n * KC;

        int s = d_order[sIdx];
        int r = __ldg(&coords[s]);
        int c = __ldg(&coords[NS + s]);
        int px = r * HW + c;

        float v = __ldg(&clusters[((size_t)nk * HW * HW) + px]);
        d_recT[((size_t)s * 32 + k) * NB + n] = v;

        if (k < 3) {
            float g = __ldg(&guidance[(((size_t)n * 3 + k) * HW * HW) + px]);
            d_recT[((size_t)s * 32 + 27 + k) * NB + n] = g;
        }
    } else if (bid < GB + ZB) {
        // ---- zero-fill output ----
        int zidx = (bid - GB) * 256 + tid;         // [0, 1048576)
        float4 z = make_float4(0.f, 0.f, 0.f, 0.f);
        #pragma unroll
        for (int it = 0; it < 8; it++) {
            int i = zidx + it * (ZB * 256);
            if (i < n4) out[i] = z;
        }
    } else {
        // ---- pair enumeration ----
        int idx = (bid - GB - ZB) * 256 + tid;     // [0, 1048576)
        int a = idx >> 10;
        int b = idx & 1023;
        if (a < NS && b < NS) {
            float dr = (float)(__ldg(&coords[a])      - __ldg(&coords[b]));
            float dc = (float)(__ldg(&coords[NS + a]) - __ldg(&coords[NS + b]));
            float cd = dr * dr + dc * dc;
            if (cd <= CD_MAX) {
                int pos = atomicAdd(&d_npairs, 1);
                if (pos < MAXP) {
                    d_pairs[pos] = ((unsigned)a << 10) | (unsigned)b;
                    d_pcd[pos]   = cd;
                }
            }
        }
    }
}

// ---------------------------------------------------------------------------
// k2: sparse compute (verbatim) — warp per pair, lane = batch, coalesced
// ---------------------------------------------------------------------------
__global__ void __launch_bounds__(256)
sparse_k(float* __restrict__ out) {
    int gw   = (blockIdx.x * blockDim.x + threadIdx.x) >> 5;
    int lane = threadIdx.x & 31;

    int np = d_npairs;
    if (np > MAXP) np = MAXP;
    if (gw >= np) return;

    unsigned pr = d_pairs[gw];
    int a = (int)(pr >> 10);
    int b = (int)(pr & 1023u);
    float cd = d_pcd[gw];

    const float* ra = d_recT + (size_t)a * 32 * NB + lane;
    const float* rb = d_recT + (size_t)b * 32 * NB + lane;

    float dot = 0.f;
    #pragma unroll
    for (int k = 0; k < KC; k++)
        dot = fmaf(__ldg(ra + k * NB), __ldg(rb + k * NB), dot);

    float gd = 0.f;
    #pragma unroll
    for (int ch = 0; ch < 3; ch++) {
        float d = __ldg(ra + (27 + ch) * NB) - __ldg(rb + (27 + ch) * NB);
        gd = fmaf(d, d, gd);
    }

    float s1 = 10.0f * __expf(-cd - gd * 3.33333333f);
    float s2 = 3.0f  * __expf(-10.0f * cd);

    out[((size_t)lane * NS + a) * NS + b] = -dot * (s1 + s2);
}

// ---------------------------------------------------------------------------
extern "C" void kernel_launch(void* const* d_in, const int* in_sizes, int n_in,
                              void* d_out, int out_size) {
    const float* guidance = (const float*)d_in[0];
    const float* clusters = (const float*)d_in[1];
    const int*   coords   = (const int*)d_in[2];
    float* out = (float*)d_out;

    prep_k<<<1, 1024>>>(coords);
    fused_k<<<NBLK, 256>>>(guidance, clusters, coords,
                           (float4*)out, out_size / 4);
    sparse_k<<<MAXP / 8, 256>>>(out);
}